// round 3
// baseline (speedup 1.0000x reference)
#include <cuda_runtime.h>

// TT-linear: y[b, n1 n2 n3] = sum_{m1 m2 m3, r1 r2}
//     x[b, m1 m2 m3] * c0[m1,n1,r1] * c1[r1,m2,n2,r2] * c2[r2,m3,n3] + bias
// B=4096, all mode dims = 16, ranks r1=r2=8.
//
// Fused per-row contraction, intermediates in shared memory only.
// 256 threads = 2 independent 128-thread row groups. Persistent grid of 152.
// Per m3-pair:
//   P1: T1[m2][n1*8+r1] = sum_m1 x[m1,m2,m3] * c0[m1,n1,r1]     (2 planes)
//   P2: T2[r2][n1*16+n2] = sum_{r1,m2} T1 * c1                   (2 planes, transposed store)
//   P3: acc[n1,n2,n3] += sum_r2 T2 * c2[r2,m3,n3]

#define XS_STRIDE 272   // 16*17 floats per m3 plane; %32=16 breaks scatter conflicts, 16B-aligned

__global__ __launch_bounds__(256, 1)
void tt_linear_kernel(const float* __restrict__ xg,
                      const float* __restrict__ c0g,
                      const float* __restrict__ c1g,
                      const float* __restrict__ c2g,
                      const float* __restrict__ biasg,
                      float* __restrict__ outg)
{
    extern __shared__ float smem[];
    // cores (shared by both groups)
    float* c0s = smem;            // 2048  : [m1*128 + n1*8 + r1]
    float* c1s = smem + 2048;     // 16384 : [(r1*16+m2)*128 + n2*8 + r2]  (same as global layout)
    float* c2s = smem + 18432;    // 2048  : [m3*128 + r2*16 + n3]  (reordered)
    // per-group buffers
    const int tid = threadIdx.x;
    const int g = tid >> 7;       // row group 0/1
    const int t = tid & 127;      // thread within group
    float* xs  = smem + 20480 + g * 12544;   // 16 planes * XS_STRIDE = 4352 : [m3][m1*16+m2]
    float* T1s = xs + 4352;                  // 2 planes * 2048 : [m2*128 + n1*8 + r1]
    float* T2t = T1s + 4096;                 // 2 planes * 2048 : [r2*256 + n1*16 + n2]

    // ---- stage cores into smem (once per CTA) ----
    for (int i = tid; i < 2048; i += 256) c0s[i] = c0g[i];
    for (int i = tid; i < 16384; i += 256) c1s[i] = c1g[i];
    for (int i = tid; i < 2048; i += 256) {
        int m3 = i >> 7;
        int r2 = (i >> 4) & 7;
        int n3 = i & 15;
        c2s[i] = c2g[r2 * 256 + m3 * 16 + n3];
    }
    __syncthreads();

    // c0 column for this thread lives in registers for the whole kernel
    float c0col[16];
#pragma unroll
    for (int m1 = 0; m1 < 16; ++m1) c0col[m1] = c0s[m1 * 128 + t];

    const int w = t >> 5;   // warp in group -> n1 block {w, w+4, w+8, w+12}
    const int j = t & 31;   // lane -> columns 4j..4j+3 of (n2*8+r2)

    const int strideR = gridDim.x * 2;
    const int iters = (4096 + strideR - 1) / strideR;  // uniform trip count (sync-safe)

    for (int it = 0; it < iters; ++it) {
        const int row = blockIdx.x * 2 + g + it * strideR;
        const bool active = row < 4096;
        const int rc = active ? row : 4095;

        // ---- load x row, transposed to [m3][m1][m2] ----
        {
            const float* xr = xg + (size_t)rc * 4096;
            for (int i = t; i < 4096; i += 128) {
                float v = xr[i];                       // coalesced LDG
                int m3 = i & 15, m2 = (i >> 4) & 15, m1 = i >> 8;
                xs[m3 * XS_STRIDE + m1 * 16 + m2] = v; // padded scatter
            }
        }
        __syncthreads();

        float acc[32];
#pragma unroll
        for (int q = 0; q < 32; ++q) acc[q] = 0.0f;

        for (int m3 = 0; m3 < 16; m3 += 2) {
            // ================= Phase 1: T1 for planes m3, m3+1 =================
            float t1a[16], t1b[16];
#pragma unroll
            for (int m2 = 0; m2 < 16; ++m2) { t1a[m2] = 0.0f; t1b[m2] = 0.0f; }
            {
                const float* xpa = xs + m3 * XS_STRIDE;
                const float* xpb = xpa + XS_STRIDE;
#pragma unroll 4
                for (int m1 = 0; m1 < 16; ++m1) {
                    const float cv = c0col[m1];
                    const float4* qa = (const float4*)(xpa + m1 * 16);
                    const float4* qb = (const float4*)(xpb + m1 * 16);
#pragma unroll
                    for (int q = 0; q < 4; ++q) {
                        float4 va = qa[q];  // broadcast LDS.128
                        float4 vb = qb[q];
                        t1a[q * 4 + 0] += va.x * cv;
                        t1a[q * 4 + 1] += va.y * cv;
                        t1a[q * 4 + 2] += va.z * cv;
                        t1a[q * 4 + 3] += va.w * cv;
                        t1b[q * 4 + 0] += vb.x * cv;
                        t1b[q * 4 + 1] += vb.y * cv;
                        t1b[q * 4 + 2] += vb.z * cv;
                        t1b[q * 4 + 3] += vb.w * cv;
                    }
                }
            }
#pragma unroll
            for (int m2 = 0; m2 < 16; ++m2) {
                T1s[m2 * 128 + t] = t1a[m2];            // conflict-free STS
                T1s[2048 + m2 * 128 + t] = t1b[m2];
            }
            __syncthreads();

            // ================= Phase 2: T2 (GEMM 16x128x128, both planes) ======
            float p2a[16], p2b[16];
#pragma unroll
            for (int q = 0; q < 16; ++q) { p2a[q] = 0.0f; p2b[q] = 0.0f; }

#pragma unroll 4
            for (int k = 0; k < 128; ++k) {              // k = r1*16 + m2
                float4 bv = *(const float4*)(c1s + k * 128 + 4 * j);  // coalesced LDS.128
                const int abase = (k & 15) * 128 + (k >> 4) + w * 8;  // m2*128 + r1 + n1base*8
#pragma unroll
                for (int i = 0; i < 4; ++i) {
                    float a0 = T1s[abase + i * 32];            // broadcast within warp
                    float a1 = T1s[2048 + abase + i * 32];
                    p2a[i * 4 + 0] += a0 * bv.x;
                    p2a[i * 4 + 1] += a0 * bv.y;
                    p2a[i * 4 + 2] += a0 * bv.z;
                    p2a[i * 4 + 3] += a0 * bv.w;
                    p2b[i * 4 + 0] += a1 * bv.x;
                    p2b[i * 4 + 1] += a1 * bv.y;
                    p2b[i * 4 + 2] += a1 * bv.z;
                    p2b[i * 4 + 3] += a1 * bv.w;
                }
            }
            // transposed store: T2t[r2*256 + n1*16 + n2]
#pragma unroll
            for (int i = 0; i < 4; ++i) {
#pragma unroll
                for (int c = 0; c < 4; ++c) {
                    const int d = 4 * j + c;                       // n2*8 + r2
                    const int addr = (d & 7) * 256 + (w + 4 * i) * 16 + (d >> 3);
                    T2t[addr] = p2a[i * 4 + c];
                    T2t[2048 + addr] = p2b[i * 4 + c];
                }
            }
            __syncthreads();

            // ================= Phase 3: accumulate output =======================
            // thread owns (n1,n2) pairs p0=t, p1=t+128; acc[0..15]=p0 n3s, acc[16..31]=p1 n3s
            float tva0[8], tva1[8], tvb0[8], tvb1[8];
#pragma unroll
            for (int r2 = 0; r2 < 8; ++r2) {
                tva0[r2] = T2t[r2 * 256 + t];          // coalesced
                tva1[r2] = T2t[r2 * 256 + t + 128];
                tvb0[r2] = T2t[2048 + r2 * 256 + t];
                tvb1[r2] = T2t[2048 + r2 * 256 + t + 128];
            }
            {
                const float* c2pa = c2s + m3 * 128;
                const float* c2pb = c2pa + 128;
#pragma unroll 2
                for (int r2 = 0; r2 < 8; ++r2) {
#pragma unroll
                    for (int n3 = 0; n3 < 16; ++n3) {
                        float ca = c2pa[r2 * 16 + n3]; // broadcast
                        float cb = c2pb[r2 * 16 + n3];
                        acc[n3]      += tva0[r2] * ca;
                        acc[n3]      += tvb0[r2] * cb;
                        acc[16 + n3] += tva1[r2] * ca;
                        acc[16 + n3] += tvb1[r2] * cb;
                    }
                }
            }
            __syncthreads();  // protect T2t before next phase-2 writes
        }

        // ---- add bias, store row ----
        if (active) {
            float* og = outg + (size_t)row * 4096;
#pragma unroll
            for (int q = 0; q < 4; ++q) {
                float4 b4 = *(const float4*)(biasg + t * 16 + 4 * q);
                float4 v;
                v.x = acc[4 * q + 0] + b4.x;
                v.y = acc[4 * q + 1] + b4.y;
                v.z = acc[4 * q + 2] + b4.z;
                v.w = acc[4 * q + 3] + b4.w;
                *(float4*)(og + t * 16 + 4 * q) = v;
            }
#pragma unroll
            for (int q = 0; q < 4; ++q) {
                float4 b4 = *(const float4*)(biasg + (t + 128) * 16 + 4 * q);
                float4 v;
                v.x = acc[16 + 4 * q + 0] + b4.x;
                v.y = acc[16 + 4 * q + 1] + b4.y;
                v.z = acc[16 + 4 * q + 2] + b4.z;
                v.w = acc[16 + 4 * q + 3] + b4.w;
                *(float4*)(og + (t + 128) * 16 + 4 * q) = v;
            }
        }
    }
}

extern "C" void kernel_launch(void* const* d_in, const int* in_sizes, int n_in,
                              void* d_out, int out_size)
{
    const float* x    = (const float*)d_in[0];
    const float* c0   = (const float*)d_in[1];
    const float* c1   = (const float*)d_in[2];
    const float* c2   = (const float*)d_in[3];
    const float* bias = (const float*)d_in[4];
    float* out = (float*)d_out;

    // 20480 (cores) + 2 * 12544 (per-group) floats = 45568 floats = 182272 bytes
    const int smem_bytes = 45568 * (int)sizeof(float);
    cudaFuncSetAttribute(tt_linear_kernel,
                         cudaFuncAttributeMaxDynamicSharedMemorySize, smem_bytes);

    tt_linear_kernel<<<152, 256, smem_bytes>>>(x, c0, c1, c2, bias, out);
}

// round 4
// speedup vs baseline: 1.3128x; 1.3128x over previous
#include <cuda_runtime.h>

// TT-linear: y[b, n1 n2 n3] = sum_{m1 m2 m3, r1 r2}
//     x[b,m1,m2,m3] * c0[m1,n1,r1] * c1[r1,m2,n2,r2] * c2[r2,m3,n3] + bias
// B=4096, modes=16, ranks 8.
//
// R4: packed fp32x2 FMAs (fma.rn.f32x2, Blackwell). Everything that was a
// pair of per-plane scalar FMAs over (m3, m3+1) becomes ONE FFMA2 on a
// plane-interleaved 64-bit operand. x / T1 / T2 / c2 are stored
// plane-interleaved in smem so packed operands come straight from LDS.64 /
// LDS.128; only the c1 operand needs a duplicate-pack (4 mov.b64 per k).

typedef unsigned long long u64;

__device__ __forceinline__ u64 pk2(float lo, float hi) {
    u64 d;
    asm("mov.b64 %0, {%1, %2};"
        : "=l"(d) : "r"(__float_as_uint(lo)), "r"(__float_as_uint(hi)));
    return d;
}
__device__ __forceinline__ float2 upk2(u64 v) {
    unsigned lo, hi;
    asm("mov.b64 {%0, %1}, %2;" : "=r"(lo), "=r"(hi) : "l"(v));
    return make_float2(__uint_as_float(lo), __uint_as_float(hi));
}
__device__ __forceinline__ u64 ffma2(u64 a, u64 b, u64 c) {
    u64 d;
    asm("fma.rn.f32x2 %0, %1, %2, %3;" : "=l"(d) : "l"(a), "l"(b), "l"(c));
    return d;
}

#define XS_PLANE 520   // floats per m3-pair plane (512 data + 8 pad), 16B-aligned stride

__global__ __launch_bounds__(256, 1)
void tt_linear_kernel(const float* __restrict__ xg,
                      const float* __restrict__ c0g,
                      const float* __restrict__ c1g,
                      const float* __restrict__ c2g,
                      const float* __restrict__ biasg,
                      float* __restrict__ outg)
{
    extern __shared__ float smem[];
    // cores (shared by both row groups)
    float* c0s = smem;            // 2048  : [m1*128 + n1*8 + r1]
    float* c1s = smem + 2048;     // 16384 : [(r1*16+m2)*128 + n2*8 + r2]
    float* c2s = smem + 18432;    // 2048  : [((m3>>1)*128 + r2*16 + n3)*2 + (m3&1)]
    const int tid = threadIdx.x;
    const int g = tid >> 7;       // row group 0/1
    const int t = tid & 127;      // thread within group
    float* xs  = smem + 20480 + g * 12352;  // 8 pair-planes * 520 : [(m3>>1)][ (m1*16+m2)*2 + (m3&1) ]
    float* T1s = xs + 4160;                 // 4096 : [(m2*128 + col)*2 + plane]
    float* T2t = T1s + 4096;                // 4096 : [(r2*256 + pos)*2 + plane]

    // ---- stage cores (once per CTA) ----
    for (int i = tid; i < 2048; i += 256) c0s[i] = c0g[i];
    for (int i = tid; i < 16384; i += 256) c1s[i] = c1g[i];
    for (int i = tid; i < 2048; i += 256) {
        int pairIdx = i >> 8;
        int within  = (i & 255) >> 1;
        int plane   = i & 1;
        int r2 = within >> 4, n3 = within & 15;
        c2s[i] = c2g[r2 * 256 + (pairIdx * 2 + plane) * 16 + n3];
    }
    __syncthreads();

    // c0 column for this thread stays in registers
    float c0col[16];
#pragma unroll
    for (int m1 = 0; m1 < 16; ++m1) c0col[m1] = c0s[m1 * 128 + t];

    const int w = t >> 5;   // warp in group -> n1 set {w, w+4, w+8, w+12}
    const int j = t & 31;   // lane -> columns 4j..4j+3 of (n2*8+r2)

    const int strideR = gridDim.x * 2;
    const int iters = (4096 + strideR - 1) / strideR;   // uniform (barrier-safe)

    for (int it = 0; it < iters; ++it) {
        const int row = blockIdx.x * 2 + g + it * strideR;
        const bool active = row < 4096;
        const int rc = active ? row : 4095;

        // ---- load x row, plane-interleaved [m3pair][(m1*16+m2)*2 + (m3&1)] ----
        {
            const float* xr = xg + (size_t)rc * 4096;
            for (int i = t; i < 4096; i += 128) {
                float v = xr[i];                            // coalesced LDG
                int m3 = i & 15, m2 = (i >> 4) & 15, m1 = i >> 8;
                xs[(m3 >> 1) * XS_PLANE + (m1 * 16 + m2) * 2 + (m3 & 1)] = v;
            }
        }
        __syncthreads();

        float acc[32];
#pragma unroll
        for (int q = 0; q < 32; ++q) acc[q] = 0.0f;

#pragma unroll 1
        for (int mp = 0; mp < 8; ++mp) {
            // ===== Phase 1: T1 pairs for planes (2mp, 2mp+1) =====
            u64 t1p[16];
#pragma unroll
            for (int m2 = 0; m2 < 16; ++m2) t1p[m2] = 0ULL;
            {
                const float* xp = xs + mp * XS_PLANE;
#pragma unroll 4
                for (int m1 = 0; m1 < 16; ++m1) {
                    const u64 cvp = pk2(c0col[m1], c0col[m1]);
                    const ulonglong2* q = (const ulonglong2*)(xp + m1 * 32);
#pragma unroll
                    for (int qq = 0; qq < 8; ++qq) {
                        ulonglong2 v = q[qq];               // broadcast LDS.128: 2 packed pairs
                        t1p[2 * qq]     = ffma2(v.x, cvp, t1p[2 * qq]);
                        t1p[2 * qq + 1] = ffma2(v.y, cvp, t1p[2 * qq + 1]);
                    }
                }
            }
#pragma unroll
            for (int m2 = 0; m2 < 16; ++m2)
                *(u64*)(T1s + (m2 * 128 + t) * 2) = t1p[m2];   // STS.64 pairs
            __syncthreads();

            // ===== Phase 2: T2 pairs (GEMM 16x128x128, both planes packed) =====
            u64 p2[16];
#pragma unroll
            for (int q = 0; q < 16; ++q) p2[q] = 0ULL;

#pragma unroll 4
            for (int k = 0; k < 128; ++k) {                 // k = r1*16 + m2
                float4 bv = *(const float4*)(c1s + k * 128 + 4 * j);  // coalesced LDS.128
                u64 bx = pk2(bv.x, bv.x);
                u64 by = pk2(bv.y, bv.y);
                u64 bz = pk2(bv.z, bv.z);
                u64 bw = pk2(bv.w, bv.w);
                const int abase = ((k & 15) * 128 + (k >> 4) + w * 8) * 2;
#pragma unroll
                for (int i = 0; i < 4; ++i) {
                    u64 ap = *(const u64*)(T1s + abase + i * 64);   // broadcast LDS.64 pair
                    p2[i * 4 + 0] = ffma2(ap, bx, p2[i * 4 + 0]);
                    p2[i * 4 + 1] = ffma2(ap, by, p2[i * 4 + 1]);
                    p2[i * 4 + 2] = ffma2(ap, bz, p2[i * 4 + 2]);
                    p2[i * 4 + 3] = ffma2(ap, bw, p2[i * 4 + 3]);
                }
            }
            // transposed pair store: T2t[(r2*256 + n1*16 + n2)*2 + plane]
#pragma unroll
            for (int i = 0; i < 4; ++i) {
#pragma unroll
                for (int c = 0; c < 4; ++c) {
                    const int d = 4 * j + c;                // n2*8 + r2
                    const int addr = ((d & 7) * 256 + (w + 4 * i) * 16 + (d >> 3)) * 2;
                    *(u64*)(T2t + addr) = p2[i * 4 + c];
                }
            }
            __syncthreads();

            // ===== Phase 3: accumulate output (packed over planes, reduce at end) =====
            u64 tv0[8], tv1[8];
#pragma unroll
            for (int r2 = 0; r2 < 8; ++r2) {
                tv0[r2] = *(const u64*)(T2t + (r2 * 256 + t) * 2);         // coalesced LDS.64
                tv1[r2] = *(const u64*)(T2t + (r2 * 256 + t + 128) * 2);
            }
            {
                const float* c2p = c2s + mp * 256;
#pragma unroll
                for (int n3 = 0; n3 < 16; ++n3) {
                    u64 a0 = 0ULL, a1 = 0ULL;
#pragma unroll
                    for (int r2 = 0; r2 < 8; ++r2) {
                        u64 cp = *(const u64*)(c2p + (r2 * 16 + n3) * 2);  // broadcast pair
                        a0 = ffma2(tv0[r2], cp, a0);
                        a1 = ffma2(tv1[r2], cp, a1);
                    }
                    float2 f0 = upk2(a0), f1 = upk2(a1);
                    acc[n3]      += f0.x + f0.y;
                    acc[16 + n3] += f1.x + f1.y;
                }
            }
            // no sync needed: T2t reads here precede the next pair's P1-end
            // barrier, which orders them against the next P2's T2t writes.
        }

        // ---- add bias, store row ----
        if (active) {
            float* og = outg + (size_t)row * 4096;
#pragma unroll
            for (int q = 0; q < 4; ++q) {
                float4 b4 = *(const float4*)(biasg + t * 16 + 4 * q);
                float4 v;
                v.x = acc[4 * q + 0] + b4.x;
                v.y = acc[4 * q + 1] + b4.y;
                v.z = acc[4 * q + 2] + b4.z;
                v.w = acc[4 * q + 3] + b4.w;
                *(float4*)(og + t * 16 + 4 * q) = v;
            }
#pragma unroll
            for (int q = 0; q < 4; ++q) {
                float4 b4 = *(const float4*)(biasg + (t + 128) * 16 + 4 * q);
                float4 v;
                v.x = acc[16 + 4 * q + 0] + b4.x;
                v.y = acc[16 + 4 * q + 1] + b4.y;
                v.z = acc[16 + 4 * q + 2] + b4.z;
                v.w = acc[16 + 4 * q + 3] + b4.w;
                *(float4*)(og + (t + 128) * 16 + 4 * q) = v;
            }
        }
    }
}

extern "C" void kernel_launch(void* const* d_in, const int* in_sizes, int n_in,
                              void* d_out, int out_size)
{
    const float* x    = (const float*)d_in[0];
    const float* c0   = (const float*)d_in[1];
    const float* c1   = (const float*)d_in[2];
    const float* c2   = (const float*)d_in[3];
    const float* bias = (const float*)d_in[4];
    float* out = (float*)d_out;

    // 20480 (cores) + 2 * 12352 (per-group xs/T1/T2) = 45184 floats = 180736 B
    const int smem_bytes = 45184 * (int)sizeof(float);
    cudaFuncSetAttribute(tt_linear_kernel,
                         cudaFuncAttributeMaxDynamicSharedMemorySize, smem_bytes);

    tt_linear_kernel<<<152, 256, smem_bytes>>>(x, c0, c1, c2, bias, out);
}

// round 5
// speedup vs baseline: 1.4575x; 1.1102x over previous
#include <cuda_runtime.h>

// TT-linear: y[b, n1 n2 n3] = sum_{m1 m2 m3, r1 r2}
//     x[b,m1,m2,m3] * c0[m1,n1,r1] * c1[r1,m2,n2,r2] * c2[r2,m3,n3] + bias
// B=4096, modes=16, ranks 8.
//
// R5: crossbar-pressure reduction on top of the R4 packed-f32x2 scheme.
//  - P2 k-loop restructured (m2 outer, r1-pairs inner): A operands arrive as
//    broadcast LDS.128 covering two k-steps (halves A-load instrs+wavefronts).
//  - c2 re-laid [n3][r2] so P3 reads ulonglong2 (halves c2 loads).
//  - per-group named barriers (bar.sync 1/2, 128) decouple the two row groups.

typedef unsigned long long u64;

__device__ __forceinline__ u64 pk2(float lo, float hi) {
    u64 d;
    asm("mov.b64 %0, {%1, %2};"
        : "=l"(d) : "r"(__float_as_uint(lo)), "r"(__float_as_uint(hi)));
    return d;
}
__device__ __forceinline__ float2 upk2(u64 v) {
    unsigned lo, hi;
    asm("mov.b64 {%0, %1}, %2;" : "=r"(lo), "=r"(hi) : "l"(v));
    return make_float2(__uint_as_float(lo), __uint_as_float(hi));
}
__device__ __forceinline__ u64 ffma2(u64 a, u64 b, u64 c) {
    u64 d;
    asm("fma.rn.f32x2 %0, %1, %2, %3;" : "=l"(d) : "l"(a), "l"(b), "l"(c));
    return d;
}
__device__ __forceinline__ void barg(int id) {
    asm volatile("bar.sync %0, 128;" :: "r"(id) : "memory");
}

#define XS_PLANE 520   // floats per m3-pair plane (512 data + 8 pad)

__global__ __launch_bounds__(256, 1)
void tt_linear_kernel(const float* __restrict__ xg,
                      const float* __restrict__ c0g,
                      const float* __restrict__ c1g,
                      const float* __restrict__ c2g,
                      const float* __restrict__ biasg,
                      float* __restrict__ outg)
{
    extern __shared__ float smem[];
    // cores (shared by both row groups)
    float* c0s = smem;            // 2048  : [m1*128 + n1*8 + r1]
    float* c1s = smem + 2048;     // 16384 : [(r1*16+m2)*128 + n2*8 + r2]
    float* c2s = smem + 18432;    // 2048  : [mp*256 + (n3*8 + r2)*2 + plane]
    const int tid = threadIdx.x;
    const int g = tid >> 7;       // row group 0/1
    const int t = tid & 127;      // thread within group
    float* xs  = smem + 20480 + g * 12352;  // 8 pair-planes * 520
    float* T1s = xs + 4160;                 // [(m2*128 + col)*2 + plane]
    float* T2t = T1s + 4096;                // [(r2*256 + pos)*2 + plane]

    // ---- stage cores (once per CTA) ----
    for (int i = tid; i < 2048; i += 256) c0s[i] = c0g[i];
    for (int i = tid; i < 16384; i += 256) c1s[i] = c1g[i];
    for (int i = tid; i < 2048; i += 256) {
        int mp = i >> 8;
        int rem = i & 255;
        int plane = rem & 1;
        int idx = rem >> 1;            // n3*8 + r2
        int n3 = idx >> 3, r2 = idx & 7;
        c2s[i] = c2g[r2 * 256 + (2 * mp + plane) * 16 + n3];
    }
    __syncthreads();

    // c0 column for this thread stays in registers
    float c0col[16];
#pragma unroll
    for (int m1 = 0; m1 < 16; ++m1) c0col[m1] = c0s[m1 * 128 + t];

    const int w = t >> 5;   // warp in group -> n1 set {w, w+4, w+8, w+12}
    const int j = t & 31;   // lane -> columns 4j..4j+3 of (n2*8+r2)
    const int mybar = g + 1;

    const int strideR = gridDim.x * 2;
    const int iters = (4096 + strideR - 1) / strideR;   // uniform (barrier-safe)

    for (int it = 0; it < iters; ++it) {
        const int row = blockIdx.x * 2 + g + it * strideR;
        const bool active = row < 4096;
        const int rc = active ? row : 4095;

        // ---- load x row, plane-interleaved [m3pair][(m1*16+m2)*2 + (m3&1)] ----
        {
            const float* xr = xg + (size_t)rc * 4096;
            for (int i = t; i < 4096; i += 128) {
                float v = xr[i];                            // coalesced LDG
                int m3 = i & 15, m2 = (i >> 4) & 15, m1 = i >> 8;
                xs[(m3 >> 1) * XS_PLANE + (m1 * 16 + m2) * 2 + (m3 & 1)] = v;
            }
        }
        barg(mybar);

        float acc[32];
#pragma unroll
        for (int q = 0; q < 32; ++q) acc[q] = 0.0f;

#pragma unroll 1
        for (int mp = 0; mp < 8; ++mp) {
            // ===== Phase 1: T1 pairs for planes (2mp, 2mp+1) =====
            u64 t1p[16];
#pragma unroll
            for (int m2 = 0; m2 < 16; ++m2) t1p[m2] = 0ULL;
            {
                const float* xp = xs + mp * XS_PLANE;
#pragma unroll 4
                for (int m1 = 0; m1 < 16; ++m1) {
                    const u64 cvp = pk2(c0col[m1], c0col[m1]);
                    const ulonglong2* q = (const ulonglong2*)(xp + m1 * 32);
#pragma unroll
                    for (int qq = 0; qq < 8; ++qq) {
                        ulonglong2 v = q[qq];               // broadcast LDS.128
                        t1p[2 * qq]     = ffma2(v.x, cvp, t1p[2 * qq]);
                        t1p[2 * qq + 1] = ffma2(v.y, cvp, t1p[2 * qq + 1]);
                    }
                }
            }
#pragma unroll
            for (int m2 = 0; m2 < 16; ++m2)
                *(u64*)(T1s + (m2 * 128 + t) * 2) = t1p[m2];   // STS.64 pairs
            barg(mybar);

            // ===== Phase 2: T2 pairs (16x128x128 GEMM, both planes packed) ====
            // k = r1*16 + m2. Loop m2 outer, r1 pairs inner: A operand for
            // (r1, r1+1) is one broadcast LDS.128 (adjacent T1 columns).
            u64 p2[16];
#pragma unroll
            for (int q = 0; q < 16; ++q) p2[q] = 0ULL;

#pragma unroll 1
            for (int m2 = 0; m2 < 16; ++m2) {
                const float* brow = c1s + m2 * 128 + 4 * j;       // + r1*2048
                const float* arow = T1s + (m2 * 128 + w * 8) * 2; // + (i*32+r1)*2
#pragma unroll
                for (int r1p = 0; r1p < 4; ++r1p) {
                    float4 bv0 = *(const float4*)(brow + (2 * r1p) * 2048);
                    float4 bv1 = *(const float4*)(brow + (2 * r1p + 1) * 2048);
                    u64 b0x = pk2(bv0.x, bv0.x), b0y = pk2(bv0.y, bv0.y);
                    u64 b0z = pk2(bv0.z, bv0.z), b0w = pk2(bv0.w, bv0.w);
                    u64 b1x = pk2(bv1.x, bv1.x), b1y = pk2(bv1.y, bv1.y);
                    u64 b1z = pk2(bv1.z, bv1.z), b1w = pk2(bv1.w, bv1.w);
#pragma unroll
                    for (int i = 0; i < 4; ++i) {
                        // pairs for r1 = 2*r1p (a2.x) and 2*r1p+1 (a2.y)
                        ulonglong2 a2 = *(const ulonglong2*)
                            (arow + (i * 32 + 2 * r1p) * 2);      // broadcast LDS.128
                        p2[i * 4 + 0] = ffma2(a2.x, b0x, p2[i * 4 + 0]);
                        p2[i * 4 + 1] = ffma2(a2.x, b0y, p2[i * 4 + 1]);
                        p2[i * 4 + 2] = ffma2(a2.x, b0z, p2[i * 4 + 2]);
                        p2[i * 4 + 3] = ffma2(a2.x, b0w, p2[i * 4 + 3]);
                        p2[i * 4 + 0] = ffma2(a2.y, b1x, p2[i * 4 + 0]);
                        p2[i * 4 + 1] = ffma2(a2.y, b1y, p2[i * 4 + 1]);
                        p2[i * 4 + 2] = ffma2(a2.y, b1z, p2[i * 4 + 2]);
                        p2[i * 4 + 3] = ffma2(a2.y, b1w, p2[i * 4 + 3]);
                    }
                }
            }
            // transposed pair store: T2t[(r2*256 + n1*16 + n2)*2 + plane]
#pragma unroll
            for (int i = 0; i < 4; ++i) {
#pragma unroll
                for (int c = 0; c < 4; ++c) {
                    const int d = 4 * j + c;                // n2*8 + r2
                    const int addr = ((d & 7) * 256 + (w + 4 * i) * 16 + (d >> 3)) * 2;
                    *(u64*)(T2t + addr) = p2[i * 4 + c];
                }
            }
            barg(mybar);

            // ===== Phase 3: accumulate output (packed planes, reduce at end) ==
            u64 tv0[8], tv1[8];
#pragma unroll
            for (int r2 = 0; r2 < 8; ++r2) {
                tv0[r2] = *(const u64*)(T2t + (r2 * 256 + t) * 2);       // coalesced
                tv1[r2] = *(const u64*)(T2t + (r2 * 256 + t + 128) * 2);
            }
            {
                const float* c2p = c2s + mp * 256;
#pragma unroll
                for (int n3 = 0; n3 < 16; ++n3) {
                    u64 a0 = 0ULL, a1 = 0ULL;
#pragma unroll
                    for (int r2p = 0; r2p < 4; ++r2p) {
                        ulonglong2 cp = *(const ulonglong2*)
                            (c2p + (n3 * 8 + 2 * r2p) * 2);   // broadcast LDS.128
                        a0 = ffma2(tv0[2 * r2p],     cp.x, a0);
                        a0 = ffma2(tv0[2 * r2p + 1], cp.y, a0);
                        a1 = ffma2(tv1[2 * r2p],     cp.x, a1);
                        a1 = ffma2(tv1[2 * r2p + 1], cp.y, a1);
                    }
                    float2 f0 = upk2(a0), f1 = upk2(a1);
                    acc[n3]      += f0.x + f0.y;
                    acc[16 + n3] += f1.x + f1.y;
                }
            }
            // no barrier needed here: P3's T2t reads precede the next pair's
            // P1-end barrier, which orders them against the next P2's writes.
        }

        // ---- add bias, store row ----
        if (active) {
            float* og = outg + (size_t)row * 4096;
#pragma unroll
            for (int q = 0; q < 4; ++q) {
                float4 b4 = *(const float4*)(biasg + t * 16 + 4 * q);
                float4 v;
                v.x = acc[4 * q + 0] + b4.x;
                v.y = acc[4 * q + 1] + b4.y;
                v.z = acc[4 * q + 2] + b4.z;
                v.w = acc[4 * q + 3] + b4.w;
                *(float4*)(og + t * 16 + 4 * q) = v;
            }
#pragma unroll
            for (int q = 0; q < 4; ++q) {
                float4 b4 = *(const float4*)(biasg + (t + 128) * 16 + 4 * q);
                float4 v;
                v.x = acc[16 + 4 * q + 0] + b4.x;
                v.y = acc[16 + 4 * q + 1] + b4.y;
                v.z = acc[16 + 4 * q + 2] + b4.z;
                v.w = acc[16 + 4 * q + 3] + b4.w;
                *(float4*)(og + (t + 128) * 16 + 4 * q) = v;
            }
        }
    }
}

extern "C" void kernel_launch(void* const* d_in, const int* in_sizes, int n_in,
                              void* d_out, int out_size)
{
    const float* x    = (const float*)d_in[0];
    const float* c0   = (const float*)d_in[1];
    const float* c1   = (const float*)d_in[2];
    const float* c2   = (const float*)d_in[3];
    const float* bias = (const float*)d_in[4];
    float* out = (float*)d_out;

    // 20480 (cores) + 2 * 12352 (per-group xs/T1/T2) = 45184 floats = 180736 B
    const int smem_bytes = 45184 * (int)sizeof(float);
    cudaFuncSetAttribute(tt_linear_kernel,
                         cudaFuncAttributeMaxDynamicSharedMemorySize, smem_bytes);

    tt_linear_kernel<<<152, 256, smem_bytes>>>(x, c0, c1, c2, bias, out);
}

// round 6
// speedup vs baseline: 1.4637x; 1.0042x over previous
#include <cuda_runtime.h>

// TT-linear, R6: fma.rn.f32x2 + 4-plane P2 + 2n1x8d thread mapping.
// y[b, n1 n2 n3] = sum x[b,m1,m2,m3] c0[m1,n1,r1] c1[r1,m2,n2,r2] c2[r2,m3,n3] + bias
// B=4096, modes 16, ranks 8. Persistent 152 CTAs x 256 thr (2 row-groups of 128).
// Per pass q (4 m3-planes = 2 pair-planes pp0/pp1):
//   x load (strided LDG.128 -> pair-interleaved STS)
//   P1: T1[pp][m2, col] pairs
//   P2: T2[pp][n1,d] pairs; c1 row read ONCE for both pp (B at 512B/k floor),
//       thread owns 2 n1 x 8 d -> A-broadcast halved vs 4n1x4d
//   P3: acc += T2 x c2 (both pp)

typedef unsigned long long u64;

__device__ __forceinline__ u64 pk2(float lo, float hi) {
    u64 d;
    asm("mov.b64 %0, {%1, %2};"
        : "=l"(d) : "r"(__float_as_uint(lo)), "r"(__float_as_uint(hi)));
    return d;
}
__device__ __forceinline__ float2 upk2(u64 v) {
    unsigned lo, hi;
    asm("mov.b64 {%0, %1}, %2;" : "=r"(lo), "=r"(hi) : "l"(v));
    return make_float2(__uint_as_float(lo), __uint_as_float(hi));
}
__device__ __forceinline__ u64 ffma2(u64 a, u64 b, u64 c) {
    u64 d;
    asm("fma.rn.f32x2 %0, %1, %2, %3;" : "=l"(d) : "l"(a), "l"(b), "l"(c));
    return d;
}
__device__ __forceinline__ void barg(int id) {
    asm volatile("bar.sync %0, 128;" :: "r"(id) : "memory");
}

__global__ __launch_bounds__(256, 1)
void tt_linear_kernel(const float* __restrict__ xg,
                      const float* __restrict__ c0g,
                      const float* __restrict__ c1g,
                      const float* __restrict__ c2g,
                      const float* __restrict__ biasg,
                      float* __restrict__ outg)
{
    extern __shared__ float smem[];
    // cores (shared by both groups)
    float* c0s = smem;            // 2048  : [m1*128 + n1*8 + r1]
    float* c1s = smem + 2048;     // 16384 : [(r1*16+m2)*128 + n2*8 + r2]
    float* c2s = smem + 18432;    // 2048  : [mpg*256 + (n3*8+r2)*2 + plane]
    const int tid = threadIdx.x;
    const int g = tid >> 7;       // row group 0/1
    const int t = tid & 127;      // thread within group
    // per-group: xs 2*520, T1 2*4096, T2 2*4096  = 17424 floats
    float* xs  = smem + 20480 + g * 17424;  // [pp*520 + (m1*16+m2)*2 + plane]
    float* T1s = xs + 1040;                 // [pp*4096 + (m2*128 + col)*2 + plane]
    float* T2t = T1s + 8192;                // [pp*4096 + (r2*256 + pos)*2 + plane]

    // ---- stage cores (once per CTA) ----
    for (int i = tid; i < 2048; i += 256) c0s[i] = c0g[i];
    for (int i = tid; i < 16384; i += 256) c1s[i] = c1g[i];
    for (int i = tid; i < 2048; i += 256) {
        int mpg = i >> 8;
        int rem = i & 255;
        int plane = rem & 1;
        int idx = rem >> 1;            // n3*8 + r2
        int n3 = idx >> 3, r2 = idx & 7;
        c2s[i] = c2g[r2 * 256 + (2 * mpg + plane) * 16 + n3];
    }
    __syncthreads();

    // c0 column for this thread (col = t) stays in registers
    float c0col[16];
#pragma unroll
    for (int m1 = 0; m1 < 16; ++m1) c0col[m1] = c0s[m1 * 128 + t];

    const int w  = t >> 5;        // warp in group
    const int j  = t & 31;        // lane
    const int dc = j & 15;        // d-chunk: d in [8*dc, 8*dc+8)
    const int ih = j >> 4;        // n1 sub-select
    const int n1a = w + 4 * ih;   // thread n1 set: {n1a, n1a+8}
    const int mybar = g + 1;

    const int strideR = gridDim.x * 2;
    const int iters = (4096 + strideR - 1) / strideR;   // uniform (barrier-safe)

    for (int it = 0; it < iters; ++it) {
        const int row = blockIdx.x * 2 + g + it * strideR;
        const bool active = row < 4096;
        const int rc = active ? row : 4095;

        float acc[32];
#pragma unroll
        for (int q = 0; q < 32; ++q) acc[q] = 0.0f;

        const float4* xrow4 = (const float4*)(xg + (size_t)rc * 4096);

#pragma unroll 1
        for (int qp = 0; qp < 4; ++qp) {    // pass: planes 4qp..4qp+3
            // ---- load x for this pass, pair-interleave into xs ----
            {
                float4 v0 = xrow4[t * 4 + qp];           // (m1m2 = t)
                float4 v1 = xrow4[(t + 128) * 4 + qp];   // (m1m2 = t+128)
                *(float2*)(xs + t * 2)               = make_float2(v0.x, v0.y);
                *(float2*)(xs + 520 + t * 2)         = make_float2(v0.z, v0.w);
                *(float2*)(xs + (t + 128) * 2)       = make_float2(v1.x, v1.y);
                *(float2*)(xs + 520 + (t + 128) * 2) = make_float2(v1.z, v1.w);
            }
            barg(mybar);

            // ===== Phase 1: T1 pairs for pp = 0,1 =====
#pragma unroll
            for (int pp = 0; pp < 2; ++pp) {
                u64 t1p[16];
#pragma unroll
                for (int m2 = 0; m2 < 16; ++m2) t1p[m2] = 0ULL;
                const float* xp = xs + pp * 520;
#pragma unroll 4
                for (int m1 = 0; m1 < 16; ++m1) {
                    const u64 cvp = pk2(c0col[m1], c0col[m1]);
                    const ulonglong2* qv = (const ulonglong2*)(xp + m1 * 32);
#pragma unroll
                    for (int qq = 0; qq < 8; ++qq) {
                        ulonglong2 v = qv[qq];          // broadcast LDS.128
                        t1p[2 * qq]     = ffma2(v.x, cvp, t1p[2 * qq]);
                        t1p[2 * qq + 1] = ffma2(v.y, cvp, t1p[2 * qq + 1]);
                    }
                }
                float* T1p = T1s + pp * 4096;
#pragma unroll
                for (int m2 = 0; m2 < 16; ++m2)
                    *(u64*)(T1p + (m2 * 128 + t) * 2) = t1p[m2];
            }
            barg(mybar);

            // ===== Phase 2: both pair-planes, c1 read once =====
            // p2[pp][n1h*8 + c] : pp plane-pair, n1 = n1a + 8*n1h, d = 8*dc + c
            u64 p2[2][16];
#pragma unroll
            for (int q = 0; q < 16; ++q) { p2[0][q] = 0ULL; p2[1][q] = 0ULL; }

            {
                const float* bbase = c1s + 8 * dc;                 // + k*128
                const float* abase = T1s + (n1a * 8) * 2;          // + m2*256 (+128 n1h, +4096 pp)
#pragma unroll 1
                for (int m2 = 0; m2 < 16; ++m2) {
                    const float* bm = bbase + m2 * 128;
                    const float* am = abase + m2 * 256;
#pragma unroll
                    for (int r1p = 0; r1p < 4; ++r1p) {
                        // B: rows k0 = 2r1p*16+m2, k1 = k0+16 (r1 stride = 2048 floats)
                        const float* bk0 = bm + (2 * r1p) * 2048;
                        float4 v00 = *(const float4*)(bk0);
                        float4 v01 = *(const float4*)(bk0 + 4);
                        float4 v10 = *(const float4*)(bk0 + 2048);
                        float4 v11 = *(const float4*)(bk0 + 2048 + 4);
                        u64 b0[8], b1[8];
                        b0[0] = pk2(v00.x, v00.x); b0[1] = pk2(v00.y, v00.y);
                        b0[2] = pk2(v00.z, v00.z); b0[3] = pk2(v00.w, v00.w);
                        b0[4] = pk2(v01.x, v01.x); b0[5] = pk2(v01.y, v01.y);
                        b0[6] = pk2(v01.z, v01.z); b0[7] = pk2(v01.w, v01.w);
                        b1[0] = pk2(v10.x, v10.x); b1[1] = pk2(v10.y, v10.y);
                        b1[2] = pk2(v10.z, v10.z); b1[3] = pk2(v10.w, v10.w);
                        b1[4] = pk2(v11.x, v11.x); b1[5] = pk2(v11.y, v11.y);
                        b1[6] = pk2(v11.z, v11.z); b1[7] = pk2(v11.w, v11.w);
                        // A: pairs for (r1 = 2r1p, 2r1p+1) as one ull2 each
#pragma unroll
                        for (int pp = 0; pp < 2; ++pp) {
                            const float* ap = am + pp * 4096 + 4 * r1p;
                            ulonglong2 aA = *(const ulonglong2*)(ap);        // n1a
                            ulonglong2 aB = *(const ulonglong2*)(ap + 128);  // n1a+8
#pragma unroll
                            for (int c = 0; c < 8; ++c) {
                                p2[pp][c]     = ffma2(aA.x, b0[c], p2[pp][c]);
                                p2[pp][c]     = ffma2(aA.y, b1[c], p2[pp][c]);
                                p2[pp][8 + c] = ffma2(aB.x, b0[c], p2[pp][8 + c]);
                                p2[pp][8 + c] = ffma2(aB.y, b1[c], p2[pp][8 + c]);
                            }
                        }
                    }
                }
            }
            // transposed store: T2t[pp*4096 + ((d&7)*256 + n1*16 + (d>>3))*2]
            // d = 8*dc + c  ->  d&7 = c, d>>3 = dc
#pragma unroll
            for (int pp = 0; pp < 2; ++pp) {
                float* T2p = T2t + pp * 4096;
#pragma unroll
                for (int nh = 0; nh < 2; ++nh) {
                    const int n1 = n1a + 8 * nh;
#pragma unroll
                    for (int c = 0; c < 8; ++c) {
                        const int addr = (c * 256 + n1 * 16 + dc) * 2;
                        *(u64*)(T2p + addr) = p2[pp][nh * 8 + c];
                    }
                }
            }
            barg(mybar);

            // ===== Phase 3: accumulate output (both pp) =====
#pragma unroll
            for (int pp = 0; pp < 2; ++pp) {
                const float* T2p = T2t + pp * 4096;
                u64 tv0[8], tv1[8];
#pragma unroll
                for (int r2 = 0; r2 < 8; ++r2) {
                    tv0[r2] = *(const u64*)(T2p + (r2 * 256 + t) * 2);       // coalesced
                    tv1[r2] = *(const u64*)(T2p + (r2 * 256 + t + 128) * 2);
                }
                const float* c2p = c2s + (2 * qp + pp) * 256;
#pragma unroll
                for (int n3 = 0; n3 < 16; ++n3) {
                    u64 a0 = 0ULL, a1 = 0ULL;
#pragma unroll
                    for (int r2p = 0; r2p < 4; ++r2p) {
                        ulonglong2 cp = *(const ulonglong2*)
                            (c2p + (n3 * 8 + 2 * r2p) * 2);   // broadcast LDS.128
                        a0 = ffma2(tv0[2 * r2p],     cp.x, a0);
                        a0 = ffma2(tv0[2 * r2p + 1], cp.y, a0);
                        a1 = ffma2(tv1[2 * r2p],     cp.x, a1);
                        a1 = ffma2(tv1[2 * r2p + 1], cp.y, a1);
                    }
                    float2 f0 = upk2(a0), f1 = upk2(a1);
                    acc[n3]      += f0.x + f0.y;
                    acc[16 + n3] += f1.x + f1.y;
                }
            }
            // next pass's post-P1 barrier orders these T2t reads vs new writes;
            // the post-xload barrier orders xs reuse.
        }

        // ---- add bias, store row ----
        if (active) {
            float* og = outg + (size_t)row * 4096;
#pragma unroll
            for (int q = 0; q < 4; ++q) {
                float4 b4 = *(const float4*)(biasg + t * 16 + 4 * q);
                float4 v;
                v.x = acc[4 * q + 0] + b4.x;
                v.y = acc[4 * q + 1] + b4.y;
                v.z = acc[4 * q + 2] + b4.z;
                v.w = acc[4 * q + 3] + b4.w;
                *(float4*)(og + t * 16 + 4 * q) = v;
            }
#pragma unroll
            for (int q = 0; q < 4; ++q) {
                float4 b4 = *(const float4*)(biasg + (t + 128) * 16 + 4 * q);
                float4 v;
                v.x = acc[16 + 4 * q + 0] + b4.x;
                v.y = acc[16 + 4 * q + 1] + b4.y;
                v.z = acc[16 + 4 * q + 2] + b4.z;
                v.w = acc[16 + 4 * q + 3] + b4.w;
                *(float4*)(og + (t + 128) * 16 + 4 * q) = v;
            }
        }
    }
}

extern "C" void kernel_launch(void* const* d_in, const int* in_sizes, int n_in,
                              void* d_out, int out_size)
{
    const float* x    = (const float*)d_in[0];
    const float* c0   = (const float*)d_in[1];
    const float* c1   = (const float*)d_in[2];
    const float* c2   = (const float*)d_in[3];
    const float* bias = (const float*)d_in[4];
    float* out = (float*)d_out;

    // 20480 (cores) + 2 * 17424 (xs + T1 + T2 per group) = 55328 floats = 221312 B
    const int smem_bytes = 55328 * (int)sizeof(float);
    cudaFuncSetAttribute(tt_linear_kernel,
                         cudaFuncAttributeMaxDynamicSharedMemorySize, smem_bytes);

    tt_linear_kernel<<<152, 256, smem_bytes>>>(x, c0, c1, c2, bias, out);
}